// round 5
// baseline (speedup 1.0000x reference)
#include <cuda_runtime.h>

// MaskRCNN RPN fused kernel, ILP-2: 2 anchors/thread (same row) -> 262K threads
// for latency hiding, while sharing per-GT y-overlap across the pair.

#define B_   2
#define A_   20
#define NTOT 261888

#define OUT_SC 0
#define OUT_BX (B_ * NTOT * 2)
#define OUT_AN (OUT_BX + B_ * NTOT * 4)
#define OUT_LB (OUT_AN + B_ * NTOT * 4)

struct LvlPtrs {
    const float* cs[5];
    const float* bp[5];
};

__global__ void __launch_bounds__(256)
rpn_fused_kernel(LvlPtrs p,
                 const float* __restrict__ gt,   // B*A*4
                 const int* __restrict__ gtc,    // B (int32 as delivered)
                 float* __restrict__ out)
{
    __shared__ float s_gt[B_ * A_ * 4];
    __shared__ float s_ga[B_ * A_];
    __shared__ int   s_cnt[B_];

    int tx = threadIdx.x;
    if (tx < B_ * A_ * 4) s_gt[tx] = gt[tx];
    if (tx < B_) {
        int c = gtc[tx];
        s_cnt[tx] = (c < 0) ? 0 : (c > A_ ? A_ : c);
    }
    __syncthreads();
    if (tx < B_ * A_) {
        const float* gb = &s_gt[tx * 4];
        s_ga[tx] = __fmul_rn(__fsub_rn(gb[2], gb[0]), __fsub_rn(gb[3], gb[1]));
    }
    __syncthreads();

    int t = blockIdx.x * blockDim.x + tx;
    int gid = t * 2;                         // first of 2 anchors
    if (gid >= B_ * NTOT) return;

    int b = (gid >= NTOT) ? 1 : 0;
    int n = gid - b * NTOT;

    int lvl, offv;
    if      (n < 196608) { lvl = 0; offv = 0;      }
    else if (n < 245760) { lvl = 1; offv = 196608; }
    else if (n < 258048) { lvl = 2; offv = 245760; }
    else if (n < 261120) { lvl = 3; offv = 258048; }
    else                 { lvl = 4; offv = 261120; }

    int log2w  = 8 - lvl;
    int log2hw = 2 * log2w;
    int hw     = 1 << log2hw;

    int local = n - offv;
    int a   = local >> log2hw;
    int rem = local & (hw - 1);
    int y   = rem >> log2w;
    int x0  = rem & ((1 << log2w) - 1);      // even; same row for both anchors

    float s    = (float)(1 << (lvl + 2));
    float half = 0.5f * (s - 1.0f);
    float base = (float)(1 << (lvl + 6));
    float cy  = s * (float)y + half;
    float cx0 = s * (float)x0 + half;
    float hh = (a == 2) ? 2.0f * base : base;
    float ww = (a == 0) ? 2.0f * base : base;

    const float* csp = p.cs[lvl];
    const float* bpp = p.bp[lvl];
    int cbase = (b * 6  + a * 2) * hw + rem;
    int bbase = (b * 12 + a * 4) * hw + rem;

    float2 c0 = *reinterpret_cast<const float2*>(csp + cbase);
    float2 c1 = *reinterpret_cast<const float2*>(csp + cbase + hw);
    float2 dy = *reinterpret_cast<const float2*>(bpp + bbase);
    float2 dx = *reinterpret_cast<const float2*>(bpp + bbase + hw);
    float2 dh = *reinterpret_cast<const float2*>(bpp + bbase + 2 * hw);
    float2 dw = *reinterpret_cast<const float2*>(bpp + bbase + 3 * hw);

    long long row = (long long)b * NTOT + n;

    // scores: interleave -> one float4
    *reinterpret_cast<float4*>(out + OUT_SC + row * 2) =
        make_float4(c0.x, c1.x, c0.y, c1.y);

    float dyv[2] = {dy.x, dy.y};
    float dxv[2] = {dx.x, dx.y};
    float dhv[2] = {dh.x, dh.y};
    float dwv[2] = {dw.x, dw.y};

    float4* bx = reinterpret_cast<float4*>(out + OUT_BX + row * 4);
    float4* an = reinterpret_cast<float4*>(out + OUT_AN + row * 4);

#pragma unroll
    for (int j = 0; j < 2; ++j) {
        float cxj = cx0 + (float)j * s;
        float cyc = cy  + dyv[j] * hh;
        float cxc = cxj + dxv[j] * ww;
        float h2  = hh * __expf(dhv[j]);
        float w2  = ww * __expf(dwv[j]);
        bx[j] = make_float4(cyc - 0.5f * h2, cxc - 0.5f * w2,
                            cyc + 0.5f * h2, cxc + 0.5f * w2);
        an[j] = make_float4(cy, cxj, hh, ww);
    }

    // ---- labels ----
    float ay1 = cy - 0.5f * hh;
    float ay2 = ay1 + hh;
    float ax1_0 = cx0 - 0.5f * ww;
    float area = hh * ww;

    int cnt = s_cnt[b];
    int labm = 0;
    for (int g = 0; g < cnt; ++g) {
        int gi = b * A_ + g;
        const float* gb = &s_gt[gi * 4];
        float gy1 = gb[0], gx1 = gb[1], gy2 = gb[2], gx2 = gb[3];
        float ga = s_ga[gi];

        float yy1 = fminf(fmaxf(ay1, gy1), gy2);
        float yy2 = fminf(fmaxf(ay2, gy1), gy2);
        float oy  = yy2 - yy1;
        float thr = area + ga;
        // conservative prune: max possible inter over x is oy*ww
        if (3.0f * oy * ww < thr * 0.9999f) continue;

#pragma unroll
        for (int j = 0; j < 2; ++j) {
            float a1 = ax1_0 + (float)j * s;
            float a2 = a1 + ww;
            float xx1 = fminf(fmaxf(a1, gx1), gx2);
            float xx2 = fminf(fmaxf(a2, gx1), gx2);
            float inter = __fmul_rn(oy, __fsub_rn(xx2, xx1));
            float uni   = __fsub_rn(thr, inter);
            if (inter / uni >= 0.5f) labm |= (1 << j);
        }
        if (labm == 3) break;
    }

    *reinterpret_cast<float2*>(out + OUT_LB + row) =
        make_float2((float)(labm & 1), (float)((labm >> 1) & 1));
}

extern "C" void kernel_launch(void* const* d_in, const int* in_sizes, int n_in,
                              void* d_out, int out_size)
{
    LvlPtrs p;
    const float* gt = nullptr;
    const int* gtc = nullptr;
    const int cs_sz[5] = {786432, 196608, 49152, 12288, 3072};
    const int bp_sz[5] = {1572864, 393216, 98304, 24576, 6144};

    for (int k = 0; k < n_in; ++k) {
        int sz = in_sizes[k];
        bool matched = false;
        for (int l = 0; l < 5 && !matched; ++l) {
            if (sz == cs_sz[l]) { p.cs[l] = (const float*)d_in[k]; matched = true; }
            else if (sz == bp_sz[l]) { p.bp[l] = (const float*)d_in[k]; matched = true; }
        }
        if (!matched) {
            if (sz == B_ * A_ * 4) gt = (const float*)d_in[k];
            else if (sz == B_)     gtc = (const int*)d_in[k];
        }
    }

    float* out = (float*)d_out;
    int threads = 256;
    int total_t = (B_ * NTOT) / 2;                  // 261888
    int blocks = (total_t + threads - 1) / threads; // 1023
    rpn_fused_kernel<<<blocks, threads>>>(p, gt, gtc, out);
}

// round 6
// speedup vs baseline: 1.5143x; 1.5143x over previous
#include <cuda_runtime.h>

// MaskRCNN RPN fused kernel, ILP-2 + division-free label test.
// Labels: fl(inter/uni) >= 0.5  <=>  inter/uni >= 0.5-2^-26 (RN boundary).
// Fast path compares inter against (area+ga)/3 with +/-2e-5 guard bands;
// ambiguous band (~never) resolved with an EXACT f64 comparison, so labels
// are bit-identical to the reference.

#define B_   2
#define A_   20
#define NTOT 261888

#define OUT_SC 0
#define OUT_BX (B_ * NTOT * 2)
#define OUT_AN (OUT_BX + B_ * NTOT * 4)
#define OUT_LB (OUT_AN + B_ * NTOT * 4)

struct LvlPtrs {
    const float* cs[5];
    const float* bp[5];
};

__global__ void __launch_bounds__(256)
rpn_fused_kernel(LvlPtrs p,
                 const float* __restrict__ gt,   // B*A*4
                 const int* __restrict__ gtc,    // B (int32 as delivered)
                 float* __restrict__ out)
{
    __shared__ float4 s_gt4[B_ * A_];   // (gy1, gx1, gy2, gx2)
    __shared__ float2 s_aux[B_ * A_];   // (ga, gw)
    __shared__ int    s_cnt[B_];

    int tx = threadIdx.x;
    if (tx < B_ * A_) s_gt4[tx] = reinterpret_cast<const float4*>(gt)[tx];
    if (tx < B_) {
        int c = gtc[tx];
        s_cnt[tx] = (c < 0) ? 0 : (c > A_ ? A_ : c);
    }
    __syncthreads();
    if (tx < B_ * A_) {
        float4 g4 = s_gt4[tx];
        float gh = __fsub_rn(g4.z, g4.x);
        float gw = __fsub_rn(g4.w, g4.y);
        s_aux[tx] = make_float2(__fmul_rn(gh, gw), gw);
    }
    __syncthreads();

    int t = blockIdx.x * blockDim.x + tx;
    int gid = t * 2;
    if (gid >= B_ * NTOT) return;

    int b = (gid >= NTOT) ? 1 : 0;
    int n = gid - b * NTOT;

    int lvl, offv;
    if      (n < 196608) { lvl = 0; offv = 0;      }
    else if (n < 245760) { lvl = 1; offv = 196608; }
    else if (n < 258048) { lvl = 2; offv = 245760; }
    else if (n < 261120) { lvl = 3; offv = 258048; }
    else                 { lvl = 4; offv = 261120; }

    int log2w  = 8 - lvl;
    int log2hw = 2 * log2w;
    int hw     = 1 << log2hw;

    int local = n - offv;
    int a   = local >> log2hw;
    int rem = local & (hw - 1);
    int y   = rem >> log2w;
    int x0  = rem & ((1 << log2w) - 1);

    float s    = (float)(1 << (lvl + 2));
    float half = 0.5f * (s - 1.0f);
    float base = (float)(1 << (lvl + 6));
    float cy  = s * (float)y + half;
    float cx0 = s * (float)x0 + half;
    float hh = (a == 2) ? 2.0f * base : base;
    float ww = (a == 0) ? 2.0f * base : base;

    const float* csp = p.cs[lvl];
    const float* bpp = p.bp[lvl];
    int cbase = (b * 6  + a * 2) * hw + rem;
    int bbase = (b * 12 + a * 4) * hw + rem;

    float2 c0 = *reinterpret_cast<const float2*>(csp + cbase);
    float2 c1 = *reinterpret_cast<const float2*>(csp + cbase + hw);
    float2 dy = *reinterpret_cast<const float2*>(bpp + bbase);
    float2 dx = *reinterpret_cast<const float2*>(bpp + bbase + hw);
    float2 dh = *reinterpret_cast<const float2*>(bpp + bbase + 2 * hw);
    float2 dw = *reinterpret_cast<const float2*>(bpp + bbase + 3 * hw);

    long long row = (long long)b * NTOT + n;

    *reinterpret_cast<float4*>(out + OUT_SC + row * 2) =
        make_float4(c0.x, c1.x, c0.y, c1.y);

    float dyv[2] = {dy.x, dy.y};
    float dxv[2] = {dx.x, dx.y};
    float dhv[2] = {dh.x, dh.y};
    float dwv[2] = {dw.x, dw.y};

    float4* bx = reinterpret_cast<float4*>(out + OUT_BX + row * 4);
    float4* an = reinterpret_cast<float4*>(out + OUT_AN + row * 4);

#pragma unroll
    for (int j = 0; j < 2; ++j) {
        float cxj = cx0 + (float)j * s;
        float cyc = cy  + dyv[j] * hh;
        float cxc = cxj + dxv[j] * ww;
        float h2  = hh * __expf(dhv[j]);
        float w2  = ww * __expf(dwv[j]);
        bx[j] = make_float4(cyc - 0.5f * h2, cxc - 0.5f * w2,
                            cyc + 0.5f * h2, cxc + 0.5f * w2);
        an[j] = make_float4(cy, cxj, hh, ww);
    }

    // ---- labels (division-free, exact) ----
    float ay1 = cy - 0.5f * hh;
    float ay2 = ay1 + hh;
    float ax1_0 = cx0 - 0.5f * ww;
    float area = hh * ww;
    const float KT = 1.0f / 3.0f;
    float Ka = area * KT;

    int cnt = s_cnt[b];
    unsigned labm = 0;
    for (int g = 0; g < cnt; ++g) {
        int gi = b * A_ + g;
        float4 gb = s_gt4[gi];
        float2 ax = s_aux[gi];               // (ga, gw)
        float ga = ax.x;

        float yy1 = fminf(fmaxf(ay1, gb.x), gb.z);
        float yy2 = fminf(fmaxf(ay2, gb.x), gb.z);
        float oy  = __fsub_rn(yy2, yy1);

        float kthr  = __fmaf_rn(ga, KT, Ka);          // ~(area+ga)/3
        float oxmax = fminf(ww, ax.y);
        // conservative prune (warp-uniform): both anchors definitely negative
        if (__fmul_rn(oy, oxmax) < kthr * 0.999f) continue;

        float m_hi = kthr * 1.00002f;
        float m_lo = kthr * 0.99998f;

#pragma unroll
        for (int j = 0; j < 2; ++j) {
            float a1 = ax1_0 + (float)j * s;
            float a2 = a1 + ww;
            float xx1 = fminf(fmaxf(a1, gb.y), gb.w);
            float xx2 = fminf(fmaxf(a2, gb.y), gb.w);
            float inter = __fmul_rn(oy, __fsub_rn(xx2, xx1));
            if (inter >= m_lo) {
                if (inter >= m_hi) {
                    labm |= (1u << j);
                } else {
                    // ambiguous band: exact reference-equivalent decision
                    float thrf = __fadd_rn(area, ga);
                    float uni  = __fsub_rn(thrf, inter);
                    const double Cd = 0.5 - 0x1p-26;
                    if ((double)inter >= Cd * (double)uni) labm |= (1u << j);
                }
            }
        }
        if (labm == 3u) break;
    }

    *reinterpret_cast<float2*>(out + OUT_LB + row) =
        make_float2((float)(labm & 1u), (float)((labm >> 1) & 1u));
}

extern "C" void kernel_launch(void* const* d_in, const int* in_sizes, int n_in,
                              void* d_out, int out_size)
{
    LvlPtrs p;
    const float* gt = nullptr;
    const int* gtc = nullptr;
    const int cs_sz[5] = {786432, 196608, 49152, 12288, 3072};
    const int bp_sz[5] = {1572864, 393216, 98304, 24576, 6144};

    for (int k = 0; k < n_in; ++k) {
        int sz = in_sizes[k];
        bool matched = false;
        for (int l = 0; l < 5 && !matched; ++l) {
            if (sz == cs_sz[l]) { p.cs[l] = (const float*)d_in[k]; matched = true; }
            else if (sz == bp_sz[l]) { p.bp[l] = (const float*)d_in[k]; matched = true; }
        }
        if (!matched) {
            if (sz == B_ * A_ * 4) gt = (const float*)d_in[k];
            else if (sz == B_)     gtc = (const int*)d_in[k];
        }
    }

    float* out = (float*)d_out;
    int threads = 256;
    int total_t = (B_ * NTOT) / 2;                  // 261888
    int blocks = (total_t + threads - 1) / threads; // 1023
    rpn_fused_kernel<<<blocks, threads>>>(p, gt, gtc, out);
}